// round 6
// baseline (speedup 1.0000x reference)
#include <cuda_runtime.h>
#include <math.h>

// ---------------------------------------------------------------------------
// HistogramLoss on GB300 — compact-list + fused stats/KDE version.
//
// feature: [1, 64, 128, 128] fp32 ; label: [1, 1, 512, 512] int32 ; out: scalar
//
// Per class c, dim d:
//   miu = Σ w x / n,  var = Σ w x²/n - miu² + 1e-10,  u = (x-miu)/std
//   S[k] = Σ_q w[c,q] exp(-12.5 (k-u_q)²)   (k = -3..3)
//   hist = S/ΣS, targ = const normalized gaussian, loss = mean smooth_l1
//
// KDE via 2048-bin weighted histogram of u in [-4,4] (δ=1/256) convolved
// with a fixed 666-tap gaussian table.
//
// Pipeline:
//   k_init    : zero class counters, build G table + target
//   k_counts  : per-coarse-pixel 4x4 label counts -> dense uchar w + g_n
//   k_compact : per class, ordered compaction into packed (idx<<5 | w) list
//   k_fused   : per (c,d) block: pass1 stats over list, pass2 histogram+conv+loss
//   k_final   : scalar reduce
// ---------------------------------------------------------------------------

#define NUM_C    19
#define PC       16384          // 128*128 coarse pixels
#define DD       64
#define NB       2048           // histogram bins over u in [-4, 4]
#define MTAPS    333            // half window in bins (1.30 sigma-units: exp(-12.5*1.3^2)=7e-10)
#define GLEN     (2*MTAPS)      // 666

__device__ unsigned char g_wb[NUM_C * PC];     // dense per-class fine-pixel counts (0..16)
__device__ unsigned int  g_list[NUM_C * PC];   // packed (q<<5)|w, ordered by q
__device__ int    g_cnt[NUM_C];                // nnz per class
__device__ int    g_n[NUM_C];                  // per-class total fine-pixel counts
__device__ float  g_partial[NUM_C * DD];       // per-(c,d) smooth-l1 sum over 7 bins
__device__ float  g_G[GLEN];                   // gaussian taps
__device__ float  g_targ[7];                   // normalized target histogram

// ---------------------------------------------------------------- init ----
__global__ void k_init() {
    int t = threadIdx.x;
    if (t < NUM_C) g_n[t] = 0;
    for (int i = t; i < GLEN; i += blockDim.x) {
        float z = (332.5f - (float)i) * (1.0f / 256.0f);
        g_G[i] = expf(-12.5f * z * z);
    }
    if (t == 0) {
        float tv[7]; float s = 0.f;
        #pragma unroll
        for (int k = 0; k < 7; k++) { float kk = (float)(k - 3); tv[k] = expf(-0.5f * kk * kk); s += tv[k]; }
        #pragma unroll
        for (int k = 0; k < 7; k++) g_targ[k] = tv[k] / s;
    }
}

// -------------------------------------------------------------- counts ----
// One thread per coarse pixel: count labels in its 4x4 fine block.
__global__ __launch_bounds__(256) void k_counts(const int* __restrict__ label) {
    __shared__ int sn[NUM_C];
    int t = threadIdx.x;
    if (t < NUM_C) sn[t] = 0;
    __syncthreads();

    int q = blockIdx.x * 256 + t;           // 64 blocks * 256 = 16384
    int y = q >> 7, x = q & 127;
    const int4* lp = (const int4*)label;    // 512 ints per fine row = 128 int4
    int base = y * 512 + x;                 // int4 index of fine row 4y, col 4x

    int w[NUM_C];
    #pragma unroll
    for (int c = 0; c < NUM_C; c++) w[c] = 0;

    #pragma unroll
    for (int r = 0; r < 4; r++) {
        int4 v = lp[base + r * 128];
        #pragma unroll
        for (int c = 0; c < NUM_C; c++)
            w[c] += (v.x == c) + (v.y == c) + (v.z == c) + (v.w == c);
    }

    #pragma unroll
    for (int c = 0; c < NUM_C; c++) {
        g_wb[c * PC + q] = (unsigned char)w[c];
        atomicAdd(&sn[c], w[c]);
    }
    __syncthreads();
    if (t < NUM_C) atomicAdd(&g_n[t], sn[t]);
}

// ------------------------------------------------------------- compact ----
// One block per class: ordered compaction of nonzero-w pixels into g_list.
__global__ __launch_bounds__(256) void k_compact() {
    int c = blockIdx.x;
    int t = threadIdx.x;
    int lane = t & 31, wid = t >> 5;
    const unsigned char* __restrict__ wrow = g_wb + c * PC;
    unsigned int* __restrict__ out = g_list + c * PC;

    __shared__ int wtot[8];
    __shared__ int s_off;
    if (t == 0) s_off = 0;
    __syncthreads();

    for (int chunk = 0; chunk < PC / 256; chunk++) {
        int q = chunk * 256 + t;
        int w = wrow[q];
        bool pred = (w != 0);
        unsigned bal = __ballot_sync(0xffffffffu, pred);
        int wsum = __popc(bal);
        int wpre = __popc(bal & ((1u << lane) - 1u));
        if (lane == 0) wtot[wid] = wsum;
        __syncthreads();
        if (t == 0) {
            int run = s_off;
            #pragma unroll
            for (int i = 0; i < 8; i++) { int v = wtot[i]; wtot[i] = run; run += v; }
            s_off = run;
        }
        __syncthreads();
        if (pred) out[wtot[wid] + wpre] = ((unsigned)q << 5) | (unsigned)w;
        __syncthreads();
    }
    if (t == 0) g_cnt[c] = s_off;
}

// --------------------------------------------------------------- fused ----
// One block per (d, c):
//   pass 1: weighted mean/var over the compact list
//   pass 2: weighted histogram of u, convolve with G, smooth-l1 vs target
__global__ __launch_bounds__(256) void k_fused(const float* __restrict__ feat) {
    int d = blockIdx.x, c = blockIdx.y;
    int t = threadIdx.x;
    int lane = t & 31, wid = t >> 5;

    __shared__ float H[NB];
    __shared__ float S7[7];
    __shared__ float r1[8], r2[8];
    __shared__ float2 s_param;

    for (int i = t; i < NB; i += 256) H[i] = 0.f;

    int nnz = g_cnt[c];
    const unsigned int* __restrict__ list = g_list + c * PC;
    const float* __restrict__ xrow = feat + d * PC;

    // ---- pass 1: stats ----
    float s1 = 0.f, s2 = 0.f;
    #pragma unroll 4
    for (int i = t; i < nnz; i += 256) {
        unsigned e = list[i];
        float w = (float)(e & 31u);
        float x = xrow[e >> 5];
        float wx = w * x;
        s1 += wx;
        s2 = fmaf(wx, x, s2);
    }
    #pragma unroll
    for (int o = 16; o; o >>= 1) {
        s1 += __shfl_down_sync(0xffffffffu, s1, o);
        s2 += __shfl_down_sync(0xffffffffu, s2, o);
    }
    if (lane == 0) { r1[wid] = s1; r2[wid] = s2; }
    __syncthreads();
    if (t == 0) {
        float a = 0.f, b = 0.f;
        #pragma unroll
        for (int i = 0; i < 8; i++) { a += r1[i]; b += r2[i]; }
        float n  = (float)g_n[c];
        float ns = fmaxf(n, 1.0f);
        float miu = a / ns;
        float var = b / ns - miu * miu + 1e-10f;
        var = fmaxf(var, 1e-10f);
        float inv_std = rsqrtf(var);
        s_param = make_float2(inv_std, -miu * inv_std);
    }
    __syncthreads();
    float2 p = s_param;

    // ---- pass 2: histogram ----
    #pragma unroll 4
    for (int i = t; i < nnz; i += 256) {
        unsigned e = list[i];
        float x = xrow[e >> 5];
        float u  = fmaf(x, p.x, p.y);                // (x - miu)/std
        float jf = fmaf(u, 256.f, 1024.f);           // (u+4)*256
        jf = fminf(fmaxf(jf, 0.f), 2047.f);
        atomicAdd(&H[(int)jf], (float)(e & 31u));    // integer-valued adds: exact
    }
    __syncthreads();

    // ---- convolution: 7 KDE values ----
    if (wid < 7) {
        // bin center u_j = -4 + (j+0.5)/256 ; k = wid-3 ; center index 256*(wid+1)
        int j0 = 256 * wid + 256 - MTAPS;
        float acc = 0.f;
        for (int i = lane; i < GLEN; i += 32) {
            int j = j0 + i;
            if (j >= 0 && j < NB) acc = fmaf(g_G[i], H[j], acc);
        }
        #pragma unroll
        for (int o = 16; o; o >>= 1) acc += __shfl_down_sync(0xffffffffu, acc, o);
        if (lane == 0) S7[wid] = acc;
    }
    __syncthreads();

    if (t == 0) {
        float tot = 0.f;
        #pragma unroll
        for (int k = 0; k < 7; k++) tot += S7[k];
        float inv = 1.0f / fmaxf(tot, 1e-30f);
        float ls = 0.f;
        #pragma unroll
        for (int k = 0; k < 7; k++) {
            float dlt = S7[k] * inv - g_targ[k];
            float a = fabsf(dlt);
            ls += (a < 1.f) ? 0.5f * a * a : a - 0.5f;
        }
        g_partial[c * DD + d] = ls;
    }
}

// --------------------------------------------------------------- final ----
__global__ void k_final(float* __restrict__ out) {
    int t = threadIdx.x;
    __shared__ float sl[NUM_C], sa[NUM_C];
    if (t < NUM_C) {
        float s = 0.f;
        for (int d = 0; d < DD; d++) s += g_partial[t * DD + d];
        float act = (g_n[t] >= 1000) ? 1.f : 0.f;
        sl[t] = s * (1.0f / 448.0f) * act;   // mean over 64*7 elements, masked
        sa[t] = act;
    }
    __syncthreads();
    if (t == 0) {
        float L = 0.f, A = 0.f;
        #pragma unroll
        for (int cc = 0; cc < NUM_C; cc++) { L += sl[cc]; A += sa[cc]; }
        out[0] = L / A;
    }
}

// -------------------------------------------------------------- launch ----
extern "C" void kernel_launch(void* const* d_in, const int* in_sizes, int n_in,
                              void* d_out, int out_size) {
    const float* feat  = (const float*)d_in[0];
    const int*   label = (const int*)d_in[1];
    // robustness: identify inputs by element count (feature=1048576, label=262144)
    if (n_in >= 2 && in_sizes[0] == 262144) {
        feat  = (const float*)d_in[1];
        label = (const int*)d_in[0];
    }

    k_init<<<1, 256>>>();
    k_counts<<<64, 256>>>(label);
    k_compact<<<NUM_C, 256>>>();
    dim3 g(DD, NUM_C);
    k_fused<<<g, 256>>>(feat);
    k_final<<<1, 32>>>((float*)d_out);
}

// round 7
// speedup vs baseline: 1.4944x; 1.4944x over previous
#include <cuda_runtime.h>
#include <math.h>

// ---------------------------------------------------------------------------
// HistogramLoss on GB300 — parallel build + single-pass x-histogram KDE.
//
// feature: [1, 64, 128, 128] fp32 ; label: [1, 1, 512, 512] int32 ; out: scalar
//
// Per class c, dim d:
//   miu = Σ w x / n,  var = Σ w x²/n - miu² + 1e-10
//   S[k] = Σ_q w[c,q] exp(-12.5 ((miu + k·std - x_q)/std)²),  k = -3..3
//   hist = S/ΣS, targ = const normalized gaussian, loss = mean smooth_l1
//
// k_fused bins x directly into a fixed 3072-bin histogram ([-6,6), δ=1/256),
// derives miu/var from histogram moments, and convolves with an on-the-fly
// Gaussian (geometric recurrence, no exp per tap).
//
// Pipeline:
//   k_init  : zero counters, build target
//   k_build : per-pixel 4x4 label counts -> per-class packed lists via
//             warp-aggregated atomic reservation (order-free; sums exact)
//   k_fused : per (c,d): histogram -> moments -> 7-bin KDE -> smooth-l1
//   k_final : scalar reduce
// ---------------------------------------------------------------------------

#define NUM_C  19
#define PC     16384            // 128*128 coarse pixels
#define DD     64
#define NBX    3072             // x-histogram bins over [-6, 6), delta = 1/256
#define HWF    1.30f            // gaussian half-window in std units (exp(-12.5*1.3^2)=7e-10)

__device__ unsigned int g_list[NUM_C * PC];   // packed (q<<5)|w
__device__ int    g_cnt[NUM_C];               // entries per class
__device__ int    g_n[NUM_C];                 // per-class total fine-pixel counts
__device__ float  g_partial[NUM_C * DD];      // per-(c,d) smooth-l1 sum over 7 bins
__device__ float  g_targ[7];                  // normalized target histogram

// ---------------------------------------------------------------- init ----
__global__ void k_init() {
    int t = threadIdx.x;
    if (t < NUM_C) { g_cnt[t] = 0; g_n[t] = 0; }
    if (t == 0) {
        float tv[7]; float s = 0.f;
        #pragma unroll
        for (int k = 0; k < 7; k++) { float kk = (float)(k - 3); tv[k] = expf(-0.5f * kk * kk); s += tv[k]; }
        #pragma unroll
        for (int k = 0; k < 7; k++) g_targ[k] = tv[k] / s;
    }
}

// --------------------------------------------------------------- build ----
// One thread per coarse pixel: count labels in its 4x4 fine block, then
// warp-aggregated reservation into per-class compact lists.
__global__ __launch_bounds__(256) void k_build(const int* __restrict__ label) {
    int t = threadIdx.x;
    int lane = t & 31;
    int q = blockIdx.x * 256 + t;           // 64 blocks * 256 = 16384
    int y = q >> 7, x = q & 127;
    const int4* lp = (const int4*)label;    // 512 ints per fine row = 128 int4
    int base = y * 512 + x;                 // int4 index of fine row 4y, col 4x

    int w[NUM_C];
    #pragma unroll
    for (int c = 0; c < NUM_C; c++) w[c] = 0;

    #pragma unroll
    for (int r = 0; r < 4; r++) {
        int4 v = lp[base + r * 128];
        #pragma unroll
        for (int c = 0; c < NUM_C; c++)
            w[c] += (v.x == c) + (v.y == c) + (v.z == c) + (v.w == c);
    }

    unsigned lmask = (1u << lane) - 1u;
    #pragma unroll
    for (int c = 0; c < NUM_C; c++) {
        bool p = (w[c] != 0);
        unsigned bal = __ballot_sync(0xffffffffu, p);
        int cnt = __popc(bal);
        int tot = __reduce_add_sync(0xffffffffu, w[c]);
        if (cnt) {                                    // warp-uniform
            int seg;
            if (lane == 0) {
                seg = atomicAdd(&g_cnt[c], cnt);
                atomicAdd(&g_n[c], tot);
            }
            seg = __shfl_sync(0xffffffffu, seg, 0);
            if (p) g_list[c * PC + seg + __popc(bal & lmask)] =
                       ((unsigned)q << 5) | (unsigned)w[c];
        }
    }
}

// --------------------------------------------------------------- fused ----
// One block per (d, c): single pass over the compact list builds a weighted
// x-histogram; moments give miu/var; Gaussian convolution via geometric
// recurrence gives the 7 KDE values; smooth-l1 vs constant target.
__global__ __launch_bounds__(256) void k_fused(const float* __restrict__ feat) {
    int d = blockIdx.x, c = blockIdx.y;
    int t = threadIdx.x;
    int lane = t & 31, wid = t >> 5;

    __shared__ float H[NBX];
    __shared__ float S7[7];
    __shared__ float r1[8], r2[8];
    __shared__ float s_par[4];     // A, jb0, sj (=std*256), hw (halfwin bins)

    for (int i = t; i < NBX; i += 256) H[i] = 0.f;
    __syncthreads();

    int nnz = g_cnt[c];
    const unsigned int* __restrict__ list = g_list + c * PC;
    const float* __restrict__ xrow = feat + d * PC;

    // ---- single data pass: weighted x-histogram (integer adds: exact) ----
    #pragma unroll 4
    for (int i = t; i < nnz; i += 256) {
        unsigned e = list[i];
        float x  = xrow[e >> 5];
        float jf = fmaf(x, 256.f, 1536.f);           // (x+6)*256
        jf = fminf(fmaxf(jf, 0.f), 3071.f);
        atomicAdd(&H[(int)jf], (float)(e & 31u));
    }
    __syncthreads();

    // ---- moments from histogram ----
    float s1 = 0.f, s2 = 0.f;
    for (int j = t; j < NBX; j += 256) {
        float h  = H[j];
        float xj = ((float)j - 1535.5f) * (1.0f / 256.0f);   // bin center
        s1 = fmaf(h, xj, s1);
        s2 = fmaf(h * xj, xj, s2);
    }
    #pragma unroll
    for (int o = 16; o; o >>= 1) {
        s1 += __shfl_down_sync(0xffffffffu, s1, o);
        s2 += __shfl_down_sync(0xffffffffu, s2, o);
    }
    if (lane == 0) { r1[wid] = s1; r2[wid] = s2; }
    __syncthreads();
    if (t == 0) {
        float a = 0.f, b = 0.f;
        #pragma unroll
        for (int i = 0; i < 8; i++) { a += r1[i]; b += r2[i]; }
        float n   = (float)g_n[c];
        float ns  = fmaxf(n, 1.0f);
        float miu = a / ns;
        float var = b / ns - miu * miu + 1e-10f;
        var = fmaxf(var, 1e-10f);
        float std = sqrtf(var);
        // exponent: -12.5*((b_k - x_j)/std)^2 ; in bin units A = 12.5/(var*256^2)
        s_par[0] = 12.5f / (var * 65536.0f);          // A
        s_par[1] = fmaf(miu, 256.f, 1535.5f);         // jb0: bin coord of miu
        s_par[2] = std * 256.0f;                      // sj: std in bins
        s_par[3] = HWF * std * 256.0f;                // half window in bins
    }
    __syncthreads();

    // ---- 7-bin KDE: warp wid handles k = wid-3 ----
    if (wid < 7) {
        float A  = s_par[0];
        float jb = fmaf((float)(wid - 3), s_par[2], s_par[1]);
        float hw = s_par[3];
        int jlo = max(0,        (int)ceilf(jb - hw));
        int jhi = min(NBX - 1,  (int)floorf(jb + hw));
        float acc = 0.f;
        int j = jlo + lane;
        if (j <= jhi) {
            float dd  = (float)j - jb;
            float e   = __expf(-A * dd * dd);
            float r   = __expf(-A * fmaf(64.f, dd, 1024.f));   // ratio for j -> j+32
            float c32 = __expf(-2048.f * A);                   // ratio update
            for (; j <= jhi; j += 32) {
                acc = fmaf(e, H[j], acc);
                e *= r;
                r *= c32;
            }
        }
        #pragma unroll
        for (int o = 16; o; o >>= 1) acc += __shfl_down_sync(0xffffffffu, acc, o);
        if (lane == 0) S7[wid] = acc;
    }
    __syncthreads();

    if (t == 0) {
        float tot = 0.f;
        #pragma unroll
        for (int k = 0; k < 7; k++) tot += S7[k];
        float inv = 1.0f / fmaxf(tot, 1e-30f);
        float ls = 0.f;
        #pragma unroll
        for (int k = 0; k < 7; k++) {
            float dlt = S7[k] * inv - g_targ[k];
            float aa = fabsf(dlt);
            ls += (aa < 1.f) ? 0.5f * aa * aa : aa - 0.5f;
        }
        g_partial[c * DD + d] = ls;
    }
}

// --------------------------------------------------------------- final ----
__global__ void k_final(float* __restrict__ out) {
    int t = threadIdx.x;
    __shared__ float sl[NUM_C], sa[NUM_C];
    if (t < NUM_C) {
        float s = 0.f;
        for (int d = 0; d < DD; d++) s += g_partial[t * DD + d];
        float act = (g_n[t] >= 1000) ? 1.f : 0.f;
        sl[t] = s * (1.0f / 448.0f) * act;   // mean over 64*7 elements, masked
        sa[t] = act;
    }
    __syncthreads();
    if (t == 0) {
        float L = 0.f, A = 0.f;
        #pragma unroll
        for (int cc = 0; cc < NUM_C; cc++) { L += sl[cc]; A += sa[cc]; }
        out[0] = L / A;
    }
}

// -------------------------------------------------------------- launch ----
extern "C" void kernel_launch(void* const* d_in, const int* in_sizes, int n_in,
                              void* d_out, int out_size) {
    const float* feat  = (const float*)d_in[0];
    const int*   label = (const int*)d_in[1];
    // robustness: identify inputs by element count (feature=1048576, label=262144)
    if (n_in >= 2 && in_sizes[0] == 262144) {
        feat  = (const float*)d_in[1];
        label = (const int*)d_in[0];
    }

    k_init<<<1, 32>>>();
    k_build<<<64, 256>>>(label);
    dim3 g(DD, NUM_C);
    k_fused<<<g, 256>>>(feat);
    k_final<<<1, 32>>>((float*)d_out);
}